// round 10
// baseline (speedup 1.0000x reference)
#include <cuda_runtime.h>
#include <math.h>
#include <stdint.h>

#define BB   128
#define DD   20
#define INF_ 64
#define HID  4096
#define NE   4

#define MT 32
#define NT 256
#define KT 16
#define KSPLIT 8
#define KC (HID / KSPLIT)   // 512
#define NK (KC / KT)        // 32

typedef unsigned long long u64;

// -------- scratch (no allocations allowed) --------
__device__ float g_flat[BB * INF_];
__device__ int   g_expert[BB];
__device__ int   g_counts[NE];
__device__ int   g_off[NE + 1];
__device__ int   g_order[BB];
__device__ float g_h[BB * HID];
__device__ float g_p[BB * HID];                  // final probs
__device__ float g_part[KSPLIT * BB * HID];      // split-K partials (16MB)

// -------- helpers --------
__device__ __forceinline__ u64 ffma2(u64 a, u64 b, u64 c) {
    u64 d;
    asm("fma.rn.f32x2 %0,%1,%2,%3;" : "=l"(d) : "l"(a), "l"(b), "l"(c));
    return d;
}
__device__ __forceinline__ void cp16(uint32_t dst, const float* src) {
    asm volatile("cp.async.cg.shared.global [%0],[%1],16;" :: "r"(dst), "l"(src));
}
union F2 { u64 u; float2 f; };

// ============================================================
// Kernel 1: conv1 (3x3x3, pad 1) + relu, conv2 (10x20x3x3) + relu
// -> flat(64), gate logits, argmax expert. One block per sample.
// ============================================================
__global__ void __launch_bounds__(256) conv_gate_kernel(
    const float* __restrict__ input,
    const float* __restrict__ c1w, const float* __restrict__ c1b,
    const float* __restrict__ c2w, const float* __restrict__ c2b,
    const float* __restrict__ wg)
{
    const int b = blockIdx.x;
    const int t = threadIdx.x;

    __shared__ float x_s[DD * 64];
    __shared__ float y1_s[DD * 64];
    __shared__ float w1_s[270];
    __shared__ float b1_s[10];
    __shared__ float w2_s[1800];
    __shared__ float accp[4][64];
    __shared__ float flat_s[64];
    __shared__ float wg_s[INF_ * NE];
    __shared__ float logit_s[NE];

    for (int i = t; i < DD * 64; i += 256) x_s[i] = input[b * (DD * 64) + i];
    for (int i = t; i < 270; i += 256)     w1_s[i] = c1w[i];
    if (t < 10)                            b1_s[t] = c1b[t];
    for (int i = t; i < 1800; i += 256)    w2_s[i] = c2w[i];
    if (t < INF_ * NE)                     wg_s[t] = wg[t];
    if (t < 64) { accp[0][t] = 0.f; accp[1][t] = 0.f; accp[2][t] = 0.f; accp[3][t] = 0.f; }
    __syncthreads();

    for (int c = 0; c < 10; c++) {
        for (int idx = t; idx < DD * 64; idx += 256) {
            int d = idx >> 6, h = (idx >> 3) & 7, w = idx & 7;
            float s = b1_s[c];
            #pragma unroll
            for (int kd = 0; kd < 3; kd++) {
                int dd = d + kd - 1;
                if ((unsigned)dd >= (unsigned)DD) continue;
                #pragma unroll
                for (int kh = 0; kh < 3; kh++) {
                    int hh = h + kh - 1;
                    if ((unsigned)hh >= 8u) continue;
                    #pragma unroll
                    for (int kw = 0; kw < 3; kw++) {
                        int ww2 = w + kw - 1;
                        if ((unsigned)ww2 >= 8u) continue;
                        s += x_s[dd * 64 + hh * 8 + ww2] * w1_s[c * 27 + kd * 9 + kh * 3 + kw];
                    }
                }
            }
            y1_s[idx] = fmaxf(s, 0.f);
        }
        __syncthreads();

        {
            int o = t & 63, part = t >> 6;
            int h = o >> 3, w = o & 7;
            float s = 0.f;
            for (int kd = part * 5; kd < part * 5 + 5; kd++) {
                #pragma unroll
                for (int kh = 0; kh < 3; kh++) {
                    int hh = h + kh - 1;
                    if ((unsigned)hh >= 8u) continue;
                    #pragma unroll
                    for (int kw = 0; kw < 3; kw++) {
                        int ww2 = w + kw - 1;
                        if ((unsigned)ww2 >= 8u) continue;
                        s += y1_s[kd * 64 + hh * 8 + ww2] * w2_s[(c * 20 + kd) * 9 + kh * 3 + kw];
                    }
                }
            }
            accp[part][o] += s;
        }
        __syncthreads();
    }

    if (t < 64) {
        float v = accp[0][t] + accp[1][t] + accp[2][t] + accp[3][t] + c2b[0];
        v = fmaxf(v, 0.f);
        flat_s[t] = v;
        g_flat[b * 64 + t] = v;
    }
    __syncthreads();

    if (t < NE) {
        float s = 0.f;
        #pragma unroll
        for (int i = 0; i < 64; i++) s += flat_s[i] * wg_s[i * NE + t];
        logit_s[t] = s;
    }
    __syncthreads();
    if (t == 0) {
        int best = 0; float bv = logit_s[0];
        #pragma unroll
        for (int e = 1; e < NE; e++) if (logit_s[e] > bv) { bv = logit_s[e]; best = e; }
        g_expert[b] = best;
    }
}

// ============================================================
// Kernel 2: routing + aux loss (single-thread deterministic scan)
// ============================================================
__global__ void route_kernel(float* __restrict__ aux_out)
{
    if (threadIdx.x != 0) return;
    int cnt[NE] = {0, 0, 0, 0};
    for (int b = 0; b < BB; b++) cnt[g_expert[b]]++;
    int off = 0;
    for (int e = 0; e < NE; e++) { g_off[e] = off; g_counts[e] = cnt[e]; off += cnt[e]; }
    g_off[NE] = off;
    int cur[NE];
    for (int e = 0; e < NE; e++) cur[e] = g_off[e];
    for (int b = 0; b < BB; b++) { int e = g_expert[b]; g_order[cur[e]++] = b; }

    float mean = (float)BB / (float)NE;
    float var = 0.f;
    for (int e = 0; e < NE; e++) { float d = (float)cnt[e] - mean; var += d * d; }
    var /= (float)(NE - 1);
    float cv2 = var / (mean * mean + 1e-10f);
    *aux_out = 2.f * cv2 * 1e-2f;
}

// ============================================================
// Kernel 3: expert-grouped hidden GEMM.
// h[r,n] = relu(b1[e,n] + sum_k flat[r,k] * w1[e,k,n]), MT=32, NTile=128, K=64.
// grid (HID/128, 1, 16): e = z&3, mtile = z>>2.
// ============================================================
__global__ void __launch_bounds__(256) hidden_kernel(
    const float* __restrict__ w1, const float* __restrict__ b1)
{
    __shared__ float As[INF_][MT];
    __shared__ float Ws[INF_][128];
    __shared__ int rows[MT];

    const int e  = blockIdx.z & 3;
    const int mt = blockIdx.z >> 2;
    const int cnt = g_counts[e];
    const int m0 = mt * MT;
    if (m0 >= cnt) return;
    const int n0 = blockIdx.x * 128;
    const int t = threadIdx.x;

    if (t < MT) {
        int m = m0 + t;
        rows[t] = (m < cnt) ? g_order[g_off[e] + m] : -1;
    }
    __syncthreads();

    const float* w1e = w1 + (size_t)e * INF_ * HID;

    #pragma unroll
    for (int j = 0; j < 8; j++) {
        int idx = t + j * 256;
        int m = idx & 31, k = idx >> 5;
        int r = rows[m];
        As[k][m] = (r >= 0) ? g_flat[r * INF_ + k] : 0.f;
    }
    #pragma unroll
    for (int j = 0; j < 8; j++) {
        int idx = t + j * 256;
        int kk = idx >> 5, c4 = idx & 31;
        *(float4*)&Ws[kk][c4 * 4] = *(const float4*)(w1e + (size_t)kk * HID + n0 + c4 * 4);
    }
    __syncthreads();

    const int tx = t & 31, ty = t >> 5;
    float acc[4][4];
    #pragma unroll
    for (int i = 0; i < 4; i++)
        #pragma unroll
        for (int j = 0; j < 4; j++) acc[i][j] = 0.f;

    #pragma unroll 8
    for (int kk = 0; kk < INF_; kk++) {
        float4 av = *(const float4*)&As[kk][ty * 4];
        float4 bv = *(const float4*)&Ws[kk][tx * 4];
        acc[0][0] += av.x * bv.x; acc[0][1] += av.x * bv.y; acc[0][2] += av.x * bv.z; acc[0][3] += av.x * bv.w;
        acc[1][0] += av.y * bv.x; acc[1][1] += av.y * bv.y; acc[1][2] += av.y * bv.z; acc[1][3] += av.y * bv.w;
        acc[2][0] += av.z * bv.x; acc[2][1] += av.z * bv.y; acc[2][2] += av.z * bv.z; acc[2][3] += av.z * bv.w;
        acc[3][0] += av.w * bv.x; acc[3][1] += av.w * bv.y; acc[3][2] += av.w * bv.z; acc[3][3] += av.w * bv.w;
    }

    float4 bb = *(const float4*)(b1 + (size_t)e * HID + n0 + tx * 4);
    #pragma unroll
    for (int mi = 0; mi < 4; mi++) {
        int r = rows[ty * 4 + mi];
        if (r >= 0) {
            float4 v;
            v.x = fmaxf(acc[mi][0] + bb.x, 0.f);
            v.y = fmaxf(acc[mi][1] + bb.y, 0.f);
            v.z = fmaxf(acc[mi][2] + bb.z, 0.f);
            v.w = fmaxf(acc[mi][3] + bb.w, 0.f);
            *(float4*)&g_h[(size_t)r * HID + n0 + tx * 4] = v;
        }
    }
}

// ============================================================
// Kernel 4: split-K per-expert SGEMM, f32x2 FMAs.
// Thread tile 8m x 4n (MT=32, NT=256, KT=16). A stored DUPLICATED
// ((a,a) float2 pairs) in smem; warp-broadcast LDS.128 reads (no
// crossbar cost, no pack MOVs). 2-stage cp.async pipeline, ONE sync
// per stage (wait -> sync -> issue next -> compute -> store next A).
// Static smem = 32K(B) + 8K(A) + 128 = 40.1KB.
// grid (HID/NT=16, KSPLIT=8, 16): e = z&3, mtile = z>>2.
// ============================================================
__global__ void __launch_bounds__(256, 2) gemm_kernel(const float* __restrict__ w2)
{
    __shared__ __align__(16) float Bs[2][KT][NT];      // 32KB
    __shared__ __align__(16) float Ad[2][KT][2 * MT];  // 8KB duplicated A
    __shared__ int rows[MT];

    const int e  = blockIdx.z & 3;
    const int mt = blockIdx.z >> 2;
    const int cnt = g_counts[e];
    const int m0 = mt * MT;
    if (m0 >= cnt) return;
    const int n0 = blockIdx.x * NT;
    const int kbase = blockIdx.y * KC;
    const int ks = blockIdx.y;
    const int t = threadIdx.x;

    if (t < MT) {
        int m = m0 + t;
        rows[t] = (m < cnt) ? g_order[g_off[e] + m] : -1;
    }
    __syncthreads();

    const float* w2e = w2 + (size_t)e * HID * HID;

    uint32_t bsm[2];
    bsm[0] = (uint32_t)__cvta_generic_to_shared(&Bs[0][0][0]);
    bsm[1] = (uint32_t)__cvta_generic_to_shared(&Bs[1][0][0]);

    // B copy mapping: per q in 0..3, idx = t + q*256; kk = idx>>6; c4 = idx&63.
    const int bkk[4] = { (t +   0) >> 6, (t + 256) >> 6, (t + 512) >> 6, (t + 768) >> 6 };
    const int bc4 = t & 63;

    // A loader: t<128 -> row am = t&31, k-offset akq = ((t>>5)&3)*4
    const int am = t & 31;
    const int akq = ((t >> 5) & 3) * 4;
    const bool aload = (t < 128);
    const int arow = rows[am];
    const float* asrc = (arow >= 0) ? (g_h + (size_t)arow * HID) : g_h;

    // ---- prologue: issue B stage 0; store A0 (duplicated); prefetch A1 ----
    #pragma unroll
    for (int q = 0; q < 4; q++)
        cp16(bsm[0] + (uint32_t)(bkk[q] * NT + bc4 * 4) * 4u,
             w2e + (size_t)(kbase + bkk[q]) * HID + n0 + bc4 * 4);
    asm volatile("cp.async.commit_group;");

    float4 pa = make_float4(0.f, 0.f, 0.f, 0.f);
    if (aload) {
        if (arow >= 0) pa = *(const float4*)(asrc + kbase + akq);
        *(float2*)&Ad[0][akq + 0][2 * am] = make_float2(pa.x, pa.x);
        *(float2*)&Ad[0][akq + 1][2 * am] = make_float2(pa.y, pa.y);
        *(float2*)&Ad[0][akq + 2][2 * am] = make_float2(pa.z, pa.z);
        *(float2*)&Ad[0][akq + 3][2 * am] = make_float2(pa.w, pa.w);
        pa = make_float4(0.f, 0.f, 0.f, 0.f);
        if (arow >= 0) pa = *(const float4*)(asrc + kbase + KT + akq);   // A stage 1
    }

    const int tx = t & 63, ty = t >> 6;   // 64 col-groups x 4 row-groups
    u64 acc[8][2];
    #pragma unroll
    for (int i = 0; i < 8; i++) { acc[i][0] = 0ULL; acc[i][1] = 0ULL; }

    for (int j = 0; j < NK; j++) {
        const int cur = j & 1;
        asm volatile("cp.async.wait_group 0;");
        __syncthreads();   // stage j B + Ad[j&1] visible to ALL threads

        if (j + 1 < NK) {
            const int kn = kbase + (j + 1) * KT;
            #pragma unroll
            for (int q = 0; q < 4; q++)
                cp16(bsm[cur ^ 1] + (uint32_t)(bkk[q] * NT + bc4 * 4) * 4u,
                     w2e + (size_t)(kn + bkk[q]) * HID + n0 + bc4 * 4);
            asm volatile("cp.async.commit_group;");
        }

        #pragma unroll
        for (int kk = 0; kk < KT; kk++) {
            // A: 8 duplicated pairs (64B) at float offset 16*ty; warp-broadcast
            ulonglong2 aA = *(const ulonglong2*)&Ad[cur][kk][16 * ty];       // m0,m1
            ulonglong2 aB = *(const ulonglong2*)&Ad[cur][kk][16 * ty + 4];   // m2,m3
            ulonglong2 aC = *(const ulonglong2*)&Ad[cur][kk][16 * ty + 8];   // m4,m5
            ulonglong2 aD = *(const ulonglong2*)&Ad[cur][kk][16 * ty + 12];  // m6,m7
            ulonglong2 bq = *(const ulonglong2*)&Bs[cur][kk][tx * 4];
            acc[0][0] = ffma2(aA.x, bq.x, acc[0][0]); acc[0][1] = ffma2(aA.x, bq.y, acc[0][1]);
            acc[1][0] = ffma2(aA.y, bq.x, acc[1][0]); acc[1][1] = ffma2(aA.y, bq.y, acc[1][1]);
            acc[2][0] = ffma2(aB.x, bq.x, acc[2][0]); acc[2][1] = ffma2(aB.x, bq.y, acc[2][1]);
            acc[3][0] = ffma2(aB.y, bq.x, acc[3][0]); acc[3][1] = ffma2(aB.y, bq.y, acc[3][1]);
            acc[4][0] = ffma2(aC.x, bq.x, acc[4][0]); acc[4][1] = ffma2(aC.x, bq.y, acc[4][1]);
            acc[5][0] = ffma2(aC.y, bq.x, acc[5][0]); acc[5][1] = ffma2(aC.y, bq.y, acc[5][1]);
            acc[6][0] = ffma2(aD.x, bq.x, acc[6][0]); acc[6][1] = ffma2(aD.x, bq.y, acc[6][1]);
            acc[7][0] = ffma2(aD.y, bq.x, acc[7][0]); acc[7][1] = ffma2(aD.y, bq.y, acc[7][1]);
        }

        // store A(j+1) into Ad[(j+1)&1] (its stage j-1 readers passed the
        // barrier; stage j readers use Ad[j&1]); then prefetch A(j+2).
        if (j + 1 < NK && aload) {
            *(float2*)&Ad[cur ^ 1][akq + 0][2 * am] = make_float2(pa.x, pa.x);
            *(float2*)&Ad[cur ^ 1][akq + 1][2 * am] = make_float2(pa.y, pa.y);
            *(float2*)&Ad[cur ^ 1][akq + 2][2 * am] = make_float2(pa.z, pa.z);
            *(float2*)&Ad[cur ^ 1][akq + 3][2 * am] = make_float2(pa.w, pa.w);
            if (j + 2 < NK) {
                pa = make_float4(0.f, 0.f, 0.f, 0.f);
                if (arow >= 0) pa = *(const float4*)(asrc + kbase + (j + 2) * KT + akq);
            }
        }
    }

    #pragma unroll
    for (int mi = 0; mi < 8; mi++) {
        int r = rows[ty * 8 + mi];
        if (r >= 0) {
            F2 c0, c1; c0.u = acc[mi][0]; c1.u = acc[mi][1];
            *(float4*)&g_part[((size_t)ks * BB + r) * HID + n0 + tx * 4] =
                make_float4(c0.f.x, c0.f.y, c1.f.x, c1.f.y);
        }
    }
}

// ============================================================
// Kernel 5: sum split-K partials + bias, row softmax -> g_p.
// ============================================================
__global__ void __launch_bounds__(256) softmax_kernel(const float* __restrict__ b2)
{
    const int b = blockIdx.x;
    const int t = threadIdx.x;
    __shared__ float row[HID];
    __shared__ float red[256];

    const int e = g_expert[b];
    const float* bb = b2 + (size_t)e * HID;

    float m = -INFINITY;
    for (int i = t; i < HID / 4; i += 256) {
        float4 g = ((const float4*)bb)[i];
        float4 v = g;
        #pragma unroll
        for (int s = 0; s < KSPLIT; s++) {
            float4 p = ((const float4*)(g_part + ((size_t)s * BB + b) * HID))[i];
            v.x += p.x; v.y += p.y; v.z += p.z; v.w += p.w;
        }
        ((float4*)row)[i] = v;
        m = fmaxf(m, fmaxf(fmaxf(v.x, v.y), fmaxf(v.z, v.w)));
    }
    red[t] = m; __syncthreads();
    for (int s = 128; s > 0; s >>= 1) {
        if (t < s) red[t] = fmaxf(red[t], red[t + s]);
        __syncthreads();
    }
    m = red[0]; __syncthreads();

    float sum = 0.f;
    for (int i = t; i < HID; i += 256) {
        float v = expf(row[i] - m);
        row[i] = v;
        sum += v;
    }
    red[t] = sum; __syncthreads();
    for (int s = 128; s > 0; s >>= 1) {
        if (t < s) red[t] += red[t + s];
        __syncthreads();
    }
    float inv = 1.f / red[0];
    for (int i = t; i < HID / 4; i += 256) {
        float4 v = ((const float4*)row)[i];
        v.x *= inv; v.y *= inv; v.z *= inv; v.w *= inv;
        ((float4*)(g_p + (size_t)b * HID))[i] = v;
    }
}

// ============================================================
// Kernel 6: out[b,d,i] = sigmoid( sum_j y[b,i*64+j] * input[b,d,j] )
// y_s padded to 65 floats/row -> conflict-free lane-strided reads.
// ============================================================
__global__ void __launch_bounds__(256) transform_kernel(
    const float* __restrict__ input, float* __restrict__ out)
{
    int b = blockIdx.x;
    int t = threadIdx.x;
    __shared__ float y_s[64 * 65];
    __shared__ float x_s[DD * 64];
    for (int i4 = t; i4 < HID / 4; i4 += 256) {
        float4 v = ((const float4*)(g_p + (size_t)b * HID))[i4];
        int i = i4 * 4;
        int r = i >> 6, c = i & 63;
        float* d = y_s + r * 65 + c;
        d[0] = v.x; d[1] = v.y; d[2] = v.z; d[3] = v.w;
    }
    for (int i = t; i < DD * 64; i += 256) x_s[i] = input[b * (DD * 64) + i];
    __syncthreads();

    for (int idx = t; idx < DD * 64; idx += 256) {
        int d = idx >> 6, i = idx & 63;
        const float* yr = y_s + i * 65;
        const float* xr = x_s + d * 64;
        float s = 0.f;
        #pragma unroll 16
        for (int j = 0; j < 64; j++) s += yr[j] * xr[j];
        out[b * (DD * 64) + idx] = 1.f / (1.f + expf(-s));
    }
}

// ============================================================
extern "C" void kernel_launch(void* const* d_in, const int* in_sizes, int n_in,
                              void* d_out, int out_size)
{
    const float* input = (const float*)d_in[0];
    const float* c1w   = (const float*)d_in[1];
    const float* c1b   = (const float*)d_in[2];
    const float* c2w   = (const float*)d_in[3];
    const float* c2b   = (const float*)d_in[4];
    const float* wg    = (const float*)d_in[5];
    const float* w1    = (const float*)d_in[6];
    const float* b1    = (const float*)d_in[7];
    const float* w2    = (const float*)d_in[8];
    const float* b2    = (const float*)d_in[9];
    float* out = (float*)d_out;

    conv_gate_kernel<<<BB, 256>>>(input, c1w, c1b, c2w, c2b, wg);
    route_kernel<<<1, 32>>>(out + (out_size - 1));
    hidden_kernel<<<dim3(HID / 128, 1, 16), 256>>>(w1, b1);
    gemm_kernel<<<dim3(HID / NT, KSPLIT, 16), 256>>>(w2);
    softmax_kernel<<<BB, 256>>>(b2);
    transform_kernel<<<BB, 256>>>(input, out);
}

// round 11
// speedup vs baseline: 1.1632x; 1.1632x over previous
#include <cuda_runtime.h>
#include <math.h>
#include <stdint.h>

#define BB   128
#define DD   20
#define INF_ 64
#define HID  4096
#define NE   4

#define MT 32
#define NT 256
#define KT 32
#define KSPLIT 4
#define KC (HID / KSPLIT)   // 1024
#define NK (KC / KT)        // 32

typedef unsigned long long u64;

// -------- scratch (no allocations allowed) --------
__device__ float g_flat[BB * INF_];
__device__ int   g_expert[BB];
__device__ int   g_counts[NE];
__device__ int   g_off[NE + 1];
__device__ int   g_order[BB];
__device__ float g_h[BB * HID];
__device__ float g_p[BB * HID];                  // final probs
__device__ float g_part[KSPLIT * BB * HID];      // split-K partials (8MB)

// -------- helpers --------
__device__ __forceinline__ u64 ffma2(u64 a, u64 b, u64 c) {
    u64 d;
    asm("fma.rn.f32x2 %0,%1,%2,%3;" : "=l"(d) : "l"(a), "l"(b), "l"(c));
    return d;
}
__device__ __forceinline__ u64 pack2(float x) {
    u64 r;
    asm("mov.b64 %0,{%1,%1};" : "=l"(r) : "f"(x));
    return r;
}
__device__ __forceinline__ void cp16(uint32_t dst, const float* src) {
    asm volatile("cp.async.cg.shared.global [%0],[%1],16;" :: "r"(dst), "l"(src));
}
union F2 { u64 u; float2 f; };

// ============================================================
// Kernel 1: conv1 (3x3x3, pad 1) + relu, conv2 (10x20x3x3) + relu
// -> flat(64), gate logits, argmax expert. One block per sample.
// ============================================================
__global__ void __launch_bounds__(256) conv_gate_kernel(
    const float* __restrict__ input,
    const float* __restrict__ c1w, const float* __restrict__ c1b,
    const float* __restrict__ c2w, const float* __restrict__ c2b,
    const float* __restrict__ wg)
{
    const int b = blockIdx.x;
    const int t = threadIdx.x;

    __shared__ float x_s[DD * 64];
    __shared__ float y1_s[DD * 64];
    __shared__ float w1_s[270];
    __shared__ float b1_s[10];
    __shared__ float w2_s[1800];
    __shared__ float accp[4][64];
    __shared__ float flat_s[64];
    __shared__ float wg_s[INF_ * NE];
    __shared__ float logit_s[NE];

    for (int i = t; i < DD * 64; i += 256) x_s[i] = input[b * (DD * 64) + i];
    for (int i = t; i < 270; i += 256)     w1_s[i] = c1w[i];
    if (t < 10)                            b1_s[t] = c1b[t];
    for (int i = t; i < 1800; i += 256)    w2_s[i] = c2w[i];
    if (t < INF_ * NE)                     wg_s[t] = wg[t];
    if (t < 64) { accp[0][t] = 0.f; accp[1][t] = 0.f; accp[2][t] = 0.f; accp[3][t] = 0.f; }
    __syncthreads();

    for (int c = 0; c < 10; c++) {
        for (int idx = t; idx < DD * 64; idx += 256) {
            int d = idx >> 6, h = (idx >> 3) & 7, w = idx & 7;
            float s = b1_s[c];
            #pragma unroll
            for (int kd = 0; kd < 3; kd++) {
                int dd = d + kd - 1;
                if ((unsigned)dd >= (unsigned)DD) continue;
                #pragma unroll
                for (int kh = 0; kh < 3; kh++) {
                    int hh = h + kh - 1;
                    if ((unsigned)hh >= 8u) continue;
                    #pragma unroll
                    for (int kw = 0; kw < 3; kw++) {
                        int ww2 = w + kw - 1;
                        if ((unsigned)ww2 >= 8u) continue;
                        s += x_s[dd * 64 + hh * 8 + ww2] * w1_s[c * 27 + kd * 9 + kh * 3 + kw];
                    }
                }
            }
            y1_s[idx] = fmaxf(s, 0.f);
        }
        __syncthreads();

        {
            int o = t & 63, part = t >> 6;
            int h = o >> 3, w = o & 7;
            float s = 0.f;
            for (int kd = part * 5; kd < part * 5 + 5; kd++) {
                #pragma unroll
                for (int kh = 0; kh < 3; kh++) {
                    int hh = h + kh - 1;
                    if ((unsigned)hh >= 8u) continue;
                    #pragma unroll
                    for (int kw = 0; kw < 3; kw++) {
                        int ww2 = w + kw - 1;
                        if ((unsigned)ww2 >= 8u) continue;
                        s += y1_s[kd * 64 + hh * 8 + ww2] * w2_s[(c * 20 + kd) * 9 + kh * 3 + kw];
                    }
                }
            }
            accp[part][o] += s;
        }
        __syncthreads();
    }

    if (t < 64) {
        float v = accp[0][t] + accp[1][t] + accp[2][t] + accp[3][t] + c2b[0];
        v = fmaxf(v, 0.f);
        flat_s[t] = v;
        g_flat[b * 64 + t] = v;
    }
    __syncthreads();

    if (t < NE) {
        float s = 0.f;
        #pragma unroll
        for (int i = 0; i < 64; i++) s += flat_s[i] * wg_s[i * NE + t];
        logit_s[t] = s;
    }
    __syncthreads();
    if (t == 0) {
        int best = 0; float bv = logit_s[0];
        #pragma unroll
        for (int e = 1; e < NE; e++) if (logit_s[e] > bv) { bv = logit_s[e]; best = e; }
        g_expert[b] = best;
    }
}

// ============================================================
// Kernel 2: routing + aux loss (single-thread deterministic scan)
// ============================================================
__global__ void route_kernel(float* __restrict__ aux_out)
{
    if (threadIdx.x != 0) return;
    int cnt[NE] = {0, 0, 0, 0};
    for (int b = 0; b < BB; b++) cnt[g_expert[b]]++;
    int off = 0;
    for (int e = 0; e < NE; e++) { g_off[e] = off; g_counts[e] = cnt[e]; off += cnt[e]; }
    g_off[NE] = off;
    int cur[NE];
    for (int e = 0; e < NE; e++) cur[e] = g_off[e];
    for (int b = 0; b < BB; b++) { int e = g_expert[b]; g_order[cur[e]++] = b; }

    float mean = (float)BB / (float)NE;
    float var = 0.f;
    for (int e = 0; e < NE; e++) { float d = (float)cnt[e] - mean; var += d * d; }
    var /= (float)(NE - 1);
    float cv2 = var / (mean * mean + 1e-10f);
    *aux_out = 2.f * cv2 * 1e-2f;
}

// ============================================================
// Kernel 3: expert-grouped hidden GEMM.
// h[r,n] = relu(b1[e,n] + sum_k flat[r,k] * w1[e,k,n]), MT=32, NTile=128, K=64.
// grid (HID/128, 1, 16): e = z&3, mtile = z>>2.
// ============================================================
__global__ void __launch_bounds__(256) hidden_kernel(
    const float* __restrict__ w1, const float* __restrict__ b1)
{
    __shared__ float As[INF_][MT];
    __shared__ float Ws[INF_][128];
    __shared__ int rows[MT];

    const int e  = blockIdx.z & 3;
    const int mt = blockIdx.z >> 2;
    const int cnt = g_counts[e];
    const int m0 = mt * MT;
    if (m0 >= cnt) return;
    const int n0 = blockIdx.x * 128;
    const int t = threadIdx.x;

    if (t < MT) {
        int m = m0 + t;
        rows[t] = (m < cnt) ? g_order[g_off[e] + m] : -1;
    }
    __syncthreads();

    const float* w1e = w1 + (size_t)e * INF_ * HID;

    #pragma unroll
    for (int j = 0; j < 8; j++) {
        int idx = t + j * 256;
        int m = idx & 31, k = idx >> 5;
        int r = rows[m];
        As[k][m] = (r >= 0) ? g_flat[r * INF_ + k] : 0.f;
    }
    #pragma unroll
    for (int j = 0; j < 8; j++) {
        int idx = t + j * 256;
        int kk = idx >> 5, c4 = idx & 31;
        *(float4*)&Ws[kk][c4 * 4] = *(const float4*)(w1e + (size_t)kk * HID + n0 + c4 * 4);
    }
    __syncthreads();

    const int tx = t & 31, ty = t >> 5;
    float acc[4][4];
    #pragma unroll
    for (int i = 0; i < 4; i++)
        #pragma unroll
        for (int j = 0; j < 4; j++) acc[i][j] = 0.f;

    #pragma unroll 8
    for (int kk = 0; kk < INF_; kk++) {
        float4 av = *(const float4*)&As[kk][ty * 4];
        float4 bv = *(const float4*)&Ws[kk][tx * 4];
        acc[0][0] += av.x * bv.x; acc[0][1] += av.x * bv.y; acc[0][2] += av.x * bv.z; acc[0][3] += av.x * bv.w;
        acc[1][0] += av.y * bv.x; acc[1][1] += av.y * bv.y; acc[1][2] += av.y * bv.z; acc[1][3] += av.y * bv.w;
        acc[2][0] += av.z * bv.x; acc[2][1] += av.z * bv.y; acc[2][2] += av.z * bv.z; acc[2][3] += av.z * bv.w;
        acc[3][0] += av.w * bv.x; acc[3][1] += av.w * bv.y; acc[3][2] += av.w * bv.z; acc[3][3] += av.w * bv.w;
    }

    float4 bb = *(const float4*)(b1 + (size_t)e * HID + n0 + tx * 4);
    #pragma unroll
    for (int mi = 0; mi < 4; mi++) {
        int r = rows[ty * 4 + mi];
        if (r >= 0) {
            float4 v;
            v.x = fmaxf(acc[mi][0] + bb.x, 0.f);
            v.y = fmaxf(acc[mi][1] + bb.y, 0.f);
            v.z = fmaxf(acc[mi][2] + bb.z, 0.f);
            v.w = fmaxf(acc[mi][3] + bb.w, 0.f);
            *(float4*)&g_h[(size_t)r * HID + n0 + tx * 4] = v;
        }
    }
}

// ============================================================
// Kernel 4: split-K per-expert SGEMM, f32x2 FMAs. R8 structure with
// KT=32 stages in DYNAMIC shared memory (72KB: Bs[2][32][256]=64KB +
// As[2][32][32]=8KB). Thread tile 8m x 4n; A via pack2 movs (ALU pipe,
// keeps crossbar at 6 wf/warp/kk). 2-stage cp.async pipeline, ONE sync
// per stage; stage compute (~860 cyc/warp) > copy latency -> hidden.
// grid (HID/NT=16, KSPLIT=4, 16): e = z&3, mtile = z>>2. 256 active
// blocks = one wave at 2 blocks/SM.
// ============================================================
extern __shared__ float dynsm[];

__global__ void __launch_bounds__(256, 2) gemm_kernel(const float* __restrict__ w2)
{
    float* Bs = dynsm;                       // [2][KT][NT]
    float* As = dynsm + 2 * KT * NT;         // [2][KT][MT]
    __shared__ int rows[MT];

    const int e  = blockIdx.z & 3;
    const int mt = blockIdx.z >> 2;
    const int cnt = g_counts[e];
    const int m0 = mt * MT;
    if (m0 >= cnt) return;
    const int n0 = blockIdx.x * NT;
    const int kbase = blockIdx.y * KC;
    const int ks = blockIdx.y;
    const int t = threadIdx.x;

    if (t < MT) {
        int m = m0 + t;
        rows[t] = (m < cnt) ? g_order[g_off[e] + m] : -1;
    }
    __syncthreads();

    const float* w2e = w2 + (size_t)e * HID * HID;

    const uint32_t bs_base = (uint32_t)__cvta_generic_to_shared(Bs);

    // B copy mapping: per q in 0..7, idx = t + q*256; kk = idx>>6; c4 = idx&63.
    int bkk[8];
    #pragma unroll
    for (int q = 0; q < 8; q++) bkk[q] = (t + q * 256) >> 6;
    const int bc4 = t & 63;

    // A loader: t<128 -> row am = t&31, k-offsets akq and akq+16
    const int am = t & 31;
    const int akq = ((t >> 5) & 3) * 4;
    const bool aload = (t < 128);
    const int arow = rows[am];
    const float* asrc = (arow >= 0) ? (g_h + (size_t)arow * HID) : g_h;

    // ---- prologue: issue B stage 0; store A0; prefetch A1 ----
    #pragma unroll
    for (int q = 0; q < 8; q++)
        cp16(bs_base + (uint32_t)((0 * KT + bkk[q]) * NT + bc4 * 4) * 4u,
             w2e + (size_t)(kbase + bkk[q]) * HID + n0 + bc4 * 4);
    asm volatile("cp.async.commit_group;");

    float4 pa0 = make_float4(0.f, 0.f, 0.f, 0.f);
    float4 pa1 = make_float4(0.f, 0.f, 0.f, 0.f);
    if (aload) {
        if (arow >= 0) {
            pa0 = *(const float4*)(asrc + kbase + akq);
            pa1 = *(const float4*)(asrc + kbase + 16 + akq);
        }
        As[(0 * KT + akq + 0) * MT + am] = pa0.x;
        As[(0 * KT + akq + 1) * MT + am] = pa0.y;
        As[(0 * KT + akq + 2) * MT + am] = pa0.z;
        As[(0 * KT + akq + 3) * MT + am] = pa0.w;
        As[(0 * KT + akq + 16) * MT + am] = pa1.x;
        As[(0 * KT + akq + 17) * MT + am] = pa1.y;
        As[(0 * KT + akq + 18) * MT + am] = pa1.z;
        As[(0 * KT + akq + 19) * MT + am] = pa1.w;
        pa0 = make_float4(0.f, 0.f, 0.f, 0.f);
        pa1 = make_float4(0.f, 0.f, 0.f, 0.f);
        if (arow >= 0) {
            pa0 = *(const float4*)(asrc + kbase + KT + akq);        // A stage 1
            pa1 = *(const float4*)(asrc + kbase + KT + 16 + akq);
        }
    }

    const int tx = t & 63, ty = t >> 6;   // 64 col-groups x 4 row-groups
    u64 acc[8][2];
    #pragma unroll
    for (int i = 0; i < 8; i++) { acc[i][0] = 0ULL; acc[i][1] = 0ULL; }

    for (int j = 0; j < NK; j++) {
        const int cur = j & 1;
        asm volatile("cp.async.wait_group 0;");
        __syncthreads();   // stage j B + As[j&1] visible to ALL threads

        // issue B stage j+1 into the other buffer (its readers, stage j-1,
        // all passed the barrier above); overlaps compute of stage j
        if (j + 1 < NK) {
            const int kn = kbase + (j + 1) * KT;
            const uint32_t bd = bs_base + (uint32_t)((cur ^ 1) * KT * NT) * 4u;
            #pragma unroll
            for (int q = 0; q < 8; q++)
                cp16(bd + (uint32_t)(bkk[q] * NT + bc4 * 4) * 4u,
                     w2e + (size_t)(kn + bkk[q]) * HID + n0 + bc4 * 4);
            asm volatile("cp.async.commit_group;");
        }

        const float* Asb = As + cur * KT * MT;
        const float* Bsb = Bs + cur * KT * NT;
        #pragma unroll 8
        for (int kk = 0; kk < KT; kk++) {
            float4 av0 = *(const float4*)(Asb + kk * MT + ty * 8);
            float4 av1 = *(const float4*)(Asb + kk * MT + ty * 8 + 4);
            ulonglong2 bq = *(const ulonglong2*)(Bsb + kk * NT + tx * 4);
            u64 a0 = pack2(av0.x), a1 = pack2(av0.y), a2 = pack2(av0.z), a3 = pack2(av0.w);
            u64 a4 = pack2(av1.x), a5 = pack2(av1.y), a6 = pack2(av1.z), a7 = pack2(av1.w);
            acc[0][0] = ffma2(a0, bq.x, acc[0][0]); acc[0][1] = ffma2(a0, bq.y, acc[0][1]);
            acc[1][0] = ffma2(a1, bq.x, acc[1][0]); acc[1][1] = ffma2(a1, bq.y, acc[1][1]);
            acc[2][0] = ffma2(a2, bq.x, acc[2][0]); acc[2][1] = ffma2(a2, bq.y, acc[2][1]);
            acc[3][0] = ffma2(a3, bq.x, acc[3][0]); acc[3][1] = ffma2(a3, bq.y, acc[3][1]);
            acc[4][0] = ffma2(a4, bq.x, acc[4][0]); acc[4][1] = ffma2(a4, bq.y, acc[4][1]);
            acc[5][0] = ffma2(a5, bq.x, acc[5][0]); acc[5][1] = ffma2(a5, bq.y, acc[5][1]);
            acc[6][0] = ffma2(a6, bq.x, acc[6][0]); acc[6][1] = ffma2(a6, bq.y, acc[6][1]);
            acc[7][0] = ffma2(a7, bq.x, acc[7][0]); acc[7][1] = ffma2(a7, bq.y, acc[7][1]);
        }

        // store A(j+1) into As[(j+1)&1] (its stage j-1 readers passed the
        // barrier; stage j readers use As[j&1]); then prefetch A(j+2).
        if (j + 1 < NK && aload) {
            float* Asn = As + (cur ^ 1) * KT * MT;
            Asn[(akq + 0) * MT + am] = pa0.x;
            Asn[(akq + 1) * MT + am] = pa0.y;
            Asn[(akq + 2) * MT + am] = pa0.z;
            Asn[(akq + 3) * MT + am] = pa0.w;
            Asn[(akq + 16) * MT + am] = pa1.x;
            Asn[(akq + 17) * MT + am] = pa1.y;
            Asn[(akq + 18) * MT + am] = pa1.z;
            Asn[(akq + 19) * MT + am] = pa1.w;
            if (j + 2 < NK) {
                pa0 = make_float4(0.f, 0.f, 0.f, 0.f);
                pa1 = make_float4(0.f, 0.f, 0.f, 0.f);
                if (arow >= 0) {
                    pa0 = *(const float4*)(asrc + kbase + (j + 2) * KT + akq);
                    pa1 = *(const float4*)(asrc + kbase + (j + 2) * KT + 16 + akq);
                }
            }
        }
    }

    #pragma unroll
    for (int mi = 0; mi < 8; mi++) {
        int r = rows[ty * 8 + mi];
        if (r >= 0) {
            F2 c0, c1; c0.u = acc[mi][0]; c1.u = acc[mi][1];
            *(float4*)&g_part[((size_t)ks * BB + r) * HID + n0 + tx * 4] =
                make_float4(c0.f.x, c0.f.y, c1.f.x, c1.f.y);
        }
    }
}

// ============================================================
// Kernel 5: sum split-K partials + bias, row softmax -> g_p.
// ============================================================
__global__ void __launch_bounds__(256) softmax_kernel(const float* __restrict__ b2)
{
    const int b = blockIdx.x;
    const int t = threadIdx.x;
    __shared__ float row[HID];
    __shared__ float red[256];

    const int e = g_expert[b];
    const float* bb = b2 + (size_t)e * HID;

    float m = -INFINITY;
    for (int i = t; i < HID / 4; i += 256) {
        float4 g = ((const float4*)bb)[i];
        float4 v = g;
        #pragma unroll
        for (int s = 0; s < KSPLIT; s++) {
            float4 p = ((const float4*)(g_part + ((size_t)s * BB + b) * HID))[i];
            v.x += p.x; v.y += p.y; v.z += p.z; v.w += p.w;
        }
        ((float4*)row)[i] = v;
        m = fmaxf(m, fmaxf(fmaxf(v.x, v.y), fmaxf(v.z, v.w)));
    }
    red[t] = m; __syncthreads();
    for (int s = 128; s > 0; s >>= 1) {
        if (t < s) red[t] = fmaxf(red[t], red[t + s]);
        __syncthreads();
    }
    m = red[0]; __syncthreads();

    float sum = 0.f;
    for (int i = t; i < HID; i += 256) {
        float v = expf(row[i] - m);
        row[i] = v;
        sum += v;
    }
    red[t] = sum; __syncthreads();
    for (int s = 128; s > 0; s >>= 1) {
        if (t < s) red[t] += red[t + s];
        __syncthreads();
    }
    float inv = 1.f / red[0];
    for (int i = t; i < HID / 4; i += 256) {
        float4 v = ((const float4*)row)[i];
        v.x *= inv; v.y *= inv; v.z *= inv; v.w *= inv;
        ((float4*)(g_p + (size_t)b * HID))[i] = v;
    }
}

// ============================================================
// Kernel 6: out[b,d,i] = sigmoid( sum_j y[b,i*64+j] * input[b,d,j] )
// y_s padded to 65 floats/row -> conflict-free lane-strided reads.
// ============================================================
__global__ void __launch_bounds__(256) transform_kernel(
    const float* __restrict__ input, float* __restrict__ out)
{
    int b = blockIdx.x;
    int t = threadIdx.x;
    __shared__ float y_s[64 * 65];
    __shared__ float x_s[DD * 64];
    for (int i4 = t; i4 < HID / 4; i4 += 256) {
        float4 v = ((const float4*)(g_p + (size_t)b * HID))[i4];
        int i = i4 * 4;
        int r = i >> 6, c = i & 63;
        float* d = y_s + r * 65 + c;
        d[0] = v.x; d[1] = v.y; d[2] = v.z; d[3] = v.w;
    }
    for (int i = t; i < DD * 64; i += 256) x_s[i] = input[b * (DD * 64) + i];
    __syncthreads();

    for (int idx = t; idx < DD * 64; idx += 256) {
        int d = idx >> 6, i = idx & 63;
        const float* yr = y_s + i * 65;
        const float* xr = x_s + d * 64;
        float s = 0.f;
        #pragma unroll 16
        for (int j = 0; j < 64; j++) s += yr[j] * xr[j];
        out[b * (DD * 64) + idx] = 1.f / (1.f + expf(-s));
    }
}

// ============================================================
extern "C" void kernel_launch(void* const* d_in, const int* in_sizes, int n_in,
                              void* d_out, int out_size)
{
    const float* input = (const float*)d_in[0];
    const float* c1w   = (const float*)d_in[1];
    const float* c1b   = (const float*)d_in[2];
    const float* c2w   = (const float*)d_in[3];
    const float* c2b   = (const float*)d_in[4];
    const float* wg    = (const float*)d_in[5];
    const float* w1    = (const float*)d_in[6];
    const float* b1    = (const float*)d_in[7];
    const float* w2    = (const float*)d_in[8];
    const float* b2    = (const float*)d_in[9];
    float* out = (float*)d_out;

    const int gemm_smem = (2 * KT * NT + 2 * KT * MT) * 4;   // 73728 bytes
    cudaFuncSetAttribute(gemm_kernel,
                         cudaFuncAttributeMaxDynamicSharedMemorySize, gemm_smem);

    conv_gate_kernel<<<BB, 256>>>(input, c1w, c1b, c2w, c2b, wg);
    route_kernel<<<1, 32>>>(out + (out_size - 1));
    hidden_kernel<<<dim3(HID / 128, 1, 16), 256>>>(w1, b1);
    gemm_kernel<<<dim3(HID / NT, KSPLIT, 16), 256, gemm_smem>>>(w2);
    softmax_kernel<<<BB, 256>>>(b2);
    transform_kernel<<<BB, 256>>>(input, out);
}

// round 12
// speedup vs baseline: 1.2593x; 1.0826x over previous
#include <cuda_runtime.h>
#include <math.h>
#include <stdint.h>

#define BB   128
#define DD   20
#define INF_ 64
#define HID  4096
#define NE   4

// hidden-GEMM tile
#define MT 32
// w2-GEMM tile (128-thread blocks for 4-blocks/SM occupancy)
#define MTG 16
#define NT 256
#define KT 16
#define KSPLIT 4
#define KC (HID / KSPLIT)   // 1024
#define NK (KC / KT)        // 64

typedef unsigned long long u64;

// -------- scratch (no allocations allowed) --------
__device__ float g_flat[BB * INF_];
__device__ int   g_expert[BB];
__device__ int   g_counts[NE];
__device__ int   g_off[NE + 1];
__device__ int   g_order[BB];
__device__ float g_h[BB * HID];
__device__ float g_p[BB * HID];                  // final probs
__device__ float g_part[KSPLIT * BB * HID];      // split-K partials (8MB)

// -------- helpers --------
__device__ __forceinline__ u64 ffma2(u64 a, u64 b, u64 c) {
    u64 d;
    asm("fma.rn.f32x2 %0,%1,%2,%3;" : "=l"(d) : "l"(a), "l"(b), "l"(c));
    return d;
}
__device__ __forceinline__ u64 pack2(float x) {
    u64 r;
    asm("mov.b64 %0,{%1,%1};" : "=l"(r) : "f"(x));
    return r;
}
__device__ __forceinline__ void cp16(uint32_t dst, const float* src) {
    asm volatile("cp.async.cg.shared.global [%0],[%1],16;" :: "r"(dst), "l"(src));
}
union F2 { u64 u; float2 f; };

// ============================================================
// Kernel 1: conv1 (3x3x3, pad 1) + relu, conv2 (10x20x3x3) + relu
// -> flat(64), gate logits, argmax expert. One block per sample.
// ============================================================
__global__ void __launch_bounds__(256) conv_gate_kernel(
    const float* __restrict__ input,
    const float* __restrict__ c1w, const float* __restrict__ c1b,
    const float* __restrict__ c2w, const float* __restrict__ c2b,
    const float* __restrict__ wg)
{
    const int b = blockIdx.x;
    const int t = threadIdx.x;

    __shared__ float x_s[DD * 64];
    __shared__ float y1_s[DD * 64];
    __shared__ float w1_s[270];
    __shared__ float b1_s[10];
    __shared__ float w2_s[1800];
    __shared__ float accp[4][64];
    __shared__ float flat_s[64];
    __shared__ float wg_s[INF_ * NE];
    __shared__ float logit_s[NE];

    for (int i = t; i < DD * 64; i += 256) x_s[i] = input[b * (DD * 64) + i];
    for (int i = t; i < 270; i += 256)     w1_s[i] = c1w[i];
    if (t < 10)                            b1_s[t] = c1b[t];
    for (int i = t; i < 1800; i += 256)    w2_s[i] = c2w[i];
    if (t < INF_ * NE)                     wg_s[t] = wg[t];
    if (t < 64) { accp[0][t] = 0.f; accp[1][t] = 0.f; accp[2][t] = 0.f; accp[3][t] = 0.f; }
    __syncthreads();

    for (int c = 0; c < 10; c++) {
        for (int idx = t; idx < DD * 64; idx += 256) {
            int d = idx >> 6, h = (idx >> 3) & 7, w = idx & 7;
            float s = b1_s[c];
            #pragma unroll
            for (int kd = 0; kd < 3; kd++) {
                int dd = d + kd - 1;
                if ((unsigned)dd >= (unsigned)DD) continue;
                #pragma unroll
                for (int kh = 0; kh < 3; kh++) {
                    int hh = h + kh - 1;
                    if ((unsigned)hh >= 8u) continue;
                    #pragma unroll
                    for (int kw = 0; kw < 3; kw++) {
                        int ww2 = w + kw - 1;
                        if ((unsigned)ww2 >= 8u) continue;
                        s += x_s[dd * 64 + hh * 8 + ww2] * w1_s[c * 27 + kd * 9 + kh * 3 + kw];
                    }
                }
            }
            y1_s[idx] = fmaxf(s, 0.f);
        }
        __syncthreads();

        {
            int o = t & 63, part = t >> 6;
            int h = o >> 3, w = o & 7;
            float s = 0.f;
            for (int kd = part * 5; kd < part * 5 + 5; kd++) {
                #pragma unroll
                for (int kh = 0; kh < 3; kh++) {
                    int hh = h + kh - 1;
                    if ((unsigned)hh >= 8u) continue;
                    #pragma unroll
                    for (int kw = 0; kw < 3; kw++) {
                        int ww2 = w + kw - 1;
                        if ((unsigned)ww2 >= 8u) continue;
                        s += y1_s[kd * 64 + hh * 8 + ww2] * w2_s[(c * 20 + kd) * 9 + kh * 3 + kw];
                    }
                }
            }
            accp[part][o] += s;
        }
        __syncthreads();
    }

    if (t < 64) {
        float v = accp[0][t] + accp[1][t] + accp[2][t] + accp[3][t] + c2b[0];
        v = fmaxf(v, 0.f);
        flat_s[t] = v;
        g_flat[b * 64 + t] = v;
    }
    __syncthreads();

    if (t < NE) {
        float s = 0.f;
        #pragma unroll
        for (int i = 0; i < 64; i++) s += flat_s[i] * wg_s[i * NE + t];
        logit_s[t] = s;
    }
    __syncthreads();
    if (t == 0) {
        int best = 0; float bv = logit_s[0];
        #pragma unroll
        for (int e = 1; e < NE; e++) if (logit_s[e] > bv) { bv = logit_s[e]; best = e; }
        g_expert[b] = best;
    }
}

// ============================================================
// Kernel 2: routing + aux loss (single-thread deterministic scan)
// ============================================================
__global__ void route_kernel(float* __restrict__ aux_out)
{
    if (threadIdx.x != 0) return;
    int cnt[NE] = {0, 0, 0, 0};
    for (int b = 0; b < BB; b++) cnt[g_expert[b]]++;
    int off = 0;
    for (int e = 0; e < NE; e++) { g_off[e] = off; g_counts[e] = cnt[e]; off += cnt[e]; }
    g_off[NE] = off;
    int cur[NE];
    for (int e = 0; e < NE; e++) cur[e] = g_off[e];
    for (int b = 0; b < BB; b++) { int e = g_expert[b]; g_order[cur[e]++] = b; }

    float mean = (float)BB / (float)NE;
    float var = 0.f;
    for (int e = 0; e < NE; e++) { float d = (float)cnt[e] - mean; var += d * d; }
    var /= (float)(NE - 1);
    float cv2 = var / (mean * mean + 1e-10f);
    *aux_out = 2.f * cv2 * 1e-2f;
}

// ============================================================
// Kernel 3: expert-grouped hidden GEMM.
// h[r,n] = relu(b1[e,n] + sum_k flat[r,k] * w1[e,k,n]), MT=32, NTile=128, K=64.
// grid (HID/128, 1, 16): e = z&3, mtile = z>>2.
// ============================================================
__global__ void __launch_bounds__(256) hidden_kernel(
    const float* __restrict__ w1, const float* __restrict__ b1)
{
    __shared__ float As[INF_][MT];
    __shared__ float Ws[INF_][128];
    __shared__ int rows[MT];

    const int e  = blockIdx.z & 3;
    const int mt = blockIdx.z >> 2;
    const int cnt = g_counts[e];
    const int m0 = mt * MT;
    if (m0 >= cnt) return;
    const int n0 = blockIdx.x * 128;
    const int t = threadIdx.x;

    if (t < MT) {
        int m = m0 + t;
        rows[t] = (m < cnt) ? g_order[g_off[e] + m] : -1;
    }
    __syncthreads();

    const float* w1e = w1 + (size_t)e * INF_ * HID;

    #pragma unroll
    for (int j = 0; j < 8; j++) {
        int idx = t + j * 256;
        int m = idx & 31, k = idx >> 5;
        int r = rows[m];
        As[k][m] = (r >= 0) ? g_flat[r * INF_ + k] : 0.f;
    }
    #pragma unroll
    for (int j = 0; j < 8; j++) {
        int idx = t + j * 256;
        int kk = idx >> 5, c4 = idx & 31;
        *(float4*)&Ws[kk][c4 * 4] = *(const float4*)(w1e + (size_t)kk * HID + n0 + c4 * 4);
    }
    __syncthreads();

    const int tx = t & 31, ty = t >> 5;
    float acc[4][4];
    #pragma unroll
    for (int i = 0; i < 4; i++)
        #pragma unroll
        for (int j = 0; j < 4; j++) acc[i][j] = 0.f;

    #pragma unroll 8
    for (int kk = 0; kk < INF_; kk++) {
        float4 av = *(const float4*)&As[kk][ty * 4];
        float4 bv = *(const float4*)&Ws[kk][tx * 4];
        acc[0][0] += av.x * bv.x; acc[0][1] += av.x * bv.y; acc[0][2] += av.x * bv.z; acc[0][3] += av.x * bv.w;
        acc[1][0] += av.y * bv.x; acc[1][1] += av.y * bv.y; acc[1][2] += av.y * bv.z; acc[1][3] += av.y * bv.w;
        acc[2][0] += av.z * bv.x; acc[2][1] += av.z * bv.y; acc[2][2] += av.z * bv.z; acc[2][3] += av.z * bv.w;
        acc[3][0] += av.w * bv.x; acc[3][1] += av.w * bv.y; acc[3][2] += av.w * bv.z; acc[3][3] += av.w * bv.w;
    }

    float4 bb = *(const float4*)(b1 + (size_t)e * HID + n0 + tx * 4);
    #pragma unroll
    for (int mi = 0; mi < 4; mi++) {
        int r = rows[ty * 4 + mi];
        if (r >= 0) {
            float4 v;
            v.x = fmaxf(acc[mi][0] + bb.x, 0.f);
            v.y = fmaxf(acc[mi][1] + bb.y, 0.f);
            v.z = fmaxf(acc[mi][2] + bb.z, 0.f);
            v.w = fmaxf(acc[mi][3] + bb.w, 0.f);
            *(float4*)&g_h[(size_t)r * HID + n0 + tx * 4] = v;
        }
    }
}

// ============================================================
// Kernel 4: split-K per-expert SGEMM, f32x2 FMAs.
// 128-thread blocks, MTG=16, NT=256, KT=16; thread tile 8m x 4n
// (tx = t&63 col-group, ty = t>>6 row-group of 8). A via pack2 movs.
// 2-stage cp.async pipeline, ONE sync per stage. Static smem 34.1KB;
// regs*128*4 < 64K -> 4 blocks/SM, ~512-576 active blocks = ~1 wave,
// 4 warps/SMSP from 4 independent blocks (stalls cross-hidden).
// grid (16, KSPLIT, NE*8): e = z&3, mtile = z>>2.
// ============================================================
__global__ void __launch_bounds__(128, 4) gemm_kernel(const float* __restrict__ w2)
{
    __shared__ __align__(16) float Bs[2][KT][NT];    // 32KB
    __shared__ __align__(16) float As[2][KT][MTG];   // 2KB
    __shared__ int rows[MTG];

    const int e  = blockIdx.z & 3;
    const int mt = blockIdx.z >> 2;
    const int cnt = g_counts[e];
    const int m0 = mt * MTG;
    if (m0 >= cnt) return;
    const int n0 = blockIdx.x * NT;
    const int kbase = blockIdx.y * KC;
    const int ks = blockIdx.y;
    const int t = threadIdx.x;

    if (t < MTG) {
        int m = m0 + t;
        rows[t] = (m < cnt) ? g_order[g_off[e] + m] : -1;
    }
    __syncthreads();

    const float* w2e = w2 + (size_t)e * HID * HID;

    uint32_t bsm[2];
    bsm[0] = (uint32_t)__cvta_generic_to_shared(&Bs[0][0][0]);
    bsm[1] = (uint32_t)__cvta_generic_to_shared(&Bs[1][0][0]);

    // B copy mapping: per q in 0..7, idx = t + q*128; kk = idx>>6; c4 = idx&63.
    int bkk[8];
    #pragma unroll
    for (int q = 0; q < 8; q++) bkk[q] = (t + q * 128) >> 6;
    const int bc4 = t & 63;

    // A loader: t<64 -> row am = t&15, k-offset akq = ((t>>4)&3)*4
    const int am = t & 15;
    const int akq = ((t >> 4) & 3) * 4;
    const bool aload = (t < 64);
    const int arow = (am < MTG) ? rows[am] : -1;
    const float* asrc = (arow >= 0) ? (g_h + (size_t)arow * HID) : g_h;

    // ---- prologue: issue B stage 0; store A0; prefetch A1 ----
    #pragma unroll
    for (int q = 0; q < 8; q++)
        cp16(bsm[0] + (uint32_t)(bkk[q] * NT + bc4 * 4) * 4u,
             w2e + (size_t)(kbase + bkk[q]) * HID + n0 + bc4 * 4);
    asm volatile("cp.async.commit_group;");

    float4 pa = make_float4(0.f, 0.f, 0.f, 0.f);
    if (aload) {
        if (arow >= 0) pa = *(const float4*)(asrc + kbase + akq);
        As[0][akq + 0][am] = pa.x;
        As[0][akq + 1][am] = pa.y;
        As[0][akq + 2][am] = pa.z;
        As[0][akq + 3][am] = pa.w;
        pa = make_float4(0.f, 0.f, 0.f, 0.f);
        if (arow >= 0) pa = *(const float4*)(asrc + kbase + KT + akq);   // A stage 1
    }

    const int tx = t & 63, ty = t >> 6;   // 64 col-groups x 2 row-groups
    u64 acc[8][2];
    #pragma unroll
    for (int i = 0; i < 8; i++) { acc[i][0] = 0ULL; acc[i][1] = 0ULL; }

    for (int j = 0; j < NK; j++) {
        const int cur = j & 1;
        asm volatile("cp.async.wait_group 0;");
        __syncthreads();   // stage j B + As[j&1] visible to ALL threads

        // issue stage j+1 into the other buffer (its readers, stage j-1,
        // all passed the barrier above); overlaps compute of stage j
        if (j + 1 < NK) {
            const int kn = kbase + (j + 1) * KT;
            #pragma unroll
            for (int q = 0; q < 8; q++)
                cp16(bsm[cur ^ 1] + (uint32_t)(bkk[q] * NT + bc4 * 4) * 4u,
                     w2e + (size_t)(kn + bkk[q]) * HID + n0 + bc4 * 4);
            asm volatile("cp.async.commit_group;");
        }

        #pragma unroll
        for (int kk = 0; kk < KT; kk++) {
            float4 av0 = *(const float4*)&As[cur][kk][ty * 8];
            float4 av1 = *(const float4*)&As[cur][kk][ty * 8 + 4];
            ulonglong2 bq = *(const ulonglong2*)&Bs[cur][kk][tx * 4];
            u64 a0 = pack2(av0.x), a1 = pack2(av0.y), a2 = pack2(av0.z), a3 = pack2(av0.w);
            u64 a4 = pack2(av1.x), a5 = pack2(av1.y), a6 = pack2(av1.z), a7 = pack2(av1.w);
            acc[0][0] = ffma2(a0, bq.x, acc[0][0]); acc[0][1] = ffma2(a0, bq.y, acc[0][1]);
            acc[1][0] = ffma2(a1, bq.x, acc[1][0]); acc[1][1] = ffma2(a1, bq.y, acc[1][1]);
            acc[2][0] = ffma2(a2, bq.x, acc[2][0]); acc[2][1] = ffma2(a2, bq.y, acc[2][1]);
            acc[3][0] = ffma2(a3, bq.x, acc[3][0]); acc[3][1] = ffma2(a3, bq.y, acc[3][1]);
            acc[4][0] = ffma2(a4, bq.x, acc[4][0]); acc[4][1] = ffma2(a4, bq.y, acc[4][1]);
            acc[5][0] = ffma2(a5, bq.x, acc[5][0]); acc[5][1] = ffma2(a5, bq.y, acc[5][1]);
            acc[6][0] = ffma2(a6, bq.x, acc[6][0]); acc[6][1] = ffma2(a6, bq.y, acc[6][1]);
            acc[7][0] = ffma2(a7, bq.x, acc[7][0]); acc[7][1] = ffma2(a7, bq.y, acc[7][1]);
        }

        // store A(j+1) into As[(j+1)&1] (its stage j-1 readers passed the
        // barrier; stage j readers use As[j&1]); then prefetch A(j+2).
        if (j + 1 < NK && aload) {
            As[cur ^ 1][akq + 0][am] = pa.x;
            As[cur ^ 1][akq + 1][am] = pa.y;
            As[cur ^ 1][akq + 2][am] = pa.z;
            As[cur ^ 1][akq + 3][am] = pa.w;
            if (j + 2 < NK) {
                pa = make_float4(0.f, 0.f, 0.f, 0.f);
                if (arow >= 0) pa = *(const float4*)(asrc + kbase + (j + 2) * KT + akq);
            }
        }
    }

    #pragma unroll
    for (int mi = 0; mi < 8; mi++) {
        int r = rows[ty * 8 + mi];
        if (r >= 0) {
            F2 c0, c1; c0.u = acc[mi][0]; c1.u = acc[mi][1];
            *(float4*)&g_part[((size_t)ks * BB + r) * HID + n0 + tx * 4] =
                make_float4(c0.f.x, c0.f.y, c1.f.x, c1.f.y);
        }
    }
}

// ============================================================
// Kernel 5: sum split-K partials + bias, row softmax -> g_p.
// ============================================================
__global__ void __launch_bounds__(256) softmax_kernel(const float* __restrict__ b2)
{
    const int b = blockIdx.x;
    const int t = threadIdx.x;
    __shared__ float row[HID];
    __shared__ float red[256];

    const int e = g_expert[b];
    const float* bb = b2 + (size_t)e * HID;

    float m = -INFINITY;
    for (int i = t; i < HID / 4; i += 256) {
        float4 g = ((const float4*)bb)[i];
        float4 v = g;
        #pragma unroll
        for (int s = 0; s < KSPLIT; s++) {
            float4 p = ((const float4*)(g_part + ((size_t)s * BB + b) * HID))[i];
            v.x += p.x; v.y += p.y; v.z += p.z; v.w += p.w;
        }
        ((float4*)row)[i] = v;
        m = fmaxf(m, fmaxf(fmaxf(v.x, v.y), fmaxf(v.z, v.w)));
    }
    red[t] = m; __syncthreads();
    for (int s = 128; s > 0; s >>= 1) {
        if (t < s) red[t] = fmaxf(red[t], red[t + s]);
        __syncthreads();
    }
    m = red[0]; __syncthreads();

    float sum = 0.f;
    for (int i = t; i < HID; i += 256) {
        float v = expf(row[i] - m);
        row[i] = v;
        sum += v;
    }
    red[t] = sum; __syncthreads();
    for (int s = 128; s > 0; s >>= 1) {
        if (t < s) red[t] += red[t + s];
        __syncthreads();
    }
    float inv = 1.f / red[0];
    for (int i = t; i < HID / 4; i += 256) {
        float4 v = ((const float4*)row)[i];
        v.x *= inv; v.y *= inv; v.z *= inv; v.w *= inv;
        ((float4*)(g_p + (size_t)b * HID))[i] = v;
    }
}

// ============================================================
// Kernel 6: out[b,d,i] = sigmoid( sum_j y[b,i*64+j] * input[b,d,j] )
// y_s padded to 65 floats/row -> conflict-free lane-strided reads.
// ============================================================
__global__ void __launch_bounds__(256) transform_kernel(
    const float* __restrict__ input, float* __restrict__ out)
{
    int b = blockIdx.x;
    int t = threadIdx.x;
    __shared__ float y_s[64 * 65];
    __shared__ float x_s[DD * 64];
    for (int i4 = t; i4 < HID / 4; i4 += 256) {
        float4 v = ((const float4*)(g_p + (size_t)b * HID))[i4];
        int i = i4 * 4;
        int r = i >> 6, c = i & 63;
        float* d = y_s + r * 65 + c;
        d[0] = v.x; d[1] = v.y; d[2] = v.z; d[3] = v.w;
    }
    for (int i = t; i < DD * 64; i += 256) x_s[i] = input[b * (DD * 64) + i];
    __syncthreads();

    for (int idx = t; idx < DD * 64; idx += 256) {
        int d = idx >> 6, i = idx & 63;
        const float* yr = y_s + i * 65;
        const float* xr = x_s + d * 64;
        float s = 0.f;
        #pragma unroll 16
        for (int j = 0; j < 64; j++) s += yr[j] * xr[j];
        out[b * (DD * 64) + idx] = 1.f / (1.f + expf(-s));
    }
}

// ============================================================
extern "C" void kernel_launch(void* const* d_in, const int* in_sizes, int n_in,
                              void* d_out, int out_size)
{
    const float* input = (const float*)d_in[0];
    const float* c1w   = (const float*)d_in[1];
    const float* c1b   = (const float*)d_in[2];
    const float* c2w   = (const float*)d_in[3];
    const float* c2b   = (const float*)d_in[4];
    const float* wg    = (const float*)d_in[5];
    const float* w1    = (const float*)d_in[6];
    const float* b1    = (const float*)d_in[7];
    const float* w2    = (const float*)d_in[8];
    const float* b2    = (const float*)d_in[9];
    float* out = (float*)d_out;

    conv_gate_kernel<<<BB, 256>>>(input, c1w, c1b, c2w, c2b, wg);
    route_kernel<<<1, 32>>>(out + (out_size - 1));
    hidden_kernel<<<dim3(HID / 128, 1, 16), 256>>>(w1, b1);
    gemm_kernel<<<dim3(HID / NT, KSPLIT, NE * 8), 128>>>(w2);
    softmax_kernel<<<BB, 256>>>(b2);
    transform_kernel<<<BB, 256>>>(input, out);
}